// round 5
// baseline (speedup 1.0000x reference)
#include <cuda_runtime.h>

#define N_NODES 100000
#define N_EDGES 1600000
#define F_IN    128
#define F_HID   128
#define F_OUT   64

typedef unsigned long long u64;

// ---------------- packed f32x2 helpers (Blackwell double-rate fp32) ----------------
__device__ __forceinline__ u64 pack2(float lo, float hi) {
    u64 r; asm("mov.b64 %0, {%1, %2};" : "=l"(r) : "f"(lo), "f"(hi)); return r;
}
__device__ __forceinline__ void fma2(u64& d, u64 a, u64 b) {
    asm("fma.rn.f32x2 %0, %1, %2, %3;" : "=l"(d) : "l"(a), "l"(b), "l"(d));
}
__device__ __forceinline__ void unpack2(u64 v, float& lo, float& hi) {
    asm("mov.b64 {%0, %1}, %2;" : "=f"(lo), "=f"(hi) : "l"(v));
}

// ---------------- persistent host-side stream/events (created at static init,
// before the harness's memory baseline; no device alloc inside kernel_launch) ----
struct HxStreams {
    cudaStream_t s2;
    cudaEvent_t  evFork, evJoin;
    HxStreams() {
        cudaStreamCreateWithFlags(&s2, cudaStreamNonBlocking);
        cudaEventCreateWithFlags(&evFork, cudaEventDisableTiming);
        cudaEventCreateWithFlags(&evJoin, cudaEventDisableTiming);
    }
};
static HxStreams g_hx;

// ---------------- static device scratch ----------------
__device__ int   g_cnt[N_NODES];
__device__ int   g_off[N_NODES + 1];
__device__ int   g_cur[N_NODES];
__device__ int   g_srcs[N_EDGES];
__device__ float g_dinv[N_NODES];
__device__ __align__(16) float g_hs1 [N_NODES * F_HID];   // UNSCALED x@W1
__device__ __align__(16) float g_agg1[N_NODES * F_HID];   // relu(layer1 out)
__device__ __align__(16) float g_hs2 [N_NODES * F_OUT];   // dinv-scaled agg1@W2

// ---------------- CSR build ----------------
__global__ void k_zero_cnt() {
    int i = blockIdx.x * blockDim.x + threadIdx.x;
    if (i < N_NODES) g_cnt[i] = 0;
}

// edge_index is int32 on device. 4 edges per thread via int4.
__global__ void k_hist(const int* __restrict__ ei) {
    int e4 = blockIdx.x * blockDim.x + threadIdx.x;
    if (e4 * 4 < N_EDGES) {
        int4 d = *(const int4*)&ei[N_EDGES + e4 * 4];
        if ((unsigned)d.x < N_NODES) atomicAdd(&g_cnt[d.x], 1);
        if ((unsigned)d.y < N_NODES) atomicAdd(&g_cnt[d.y], 1);
        if ((unsigned)d.z < N_NODES) atomicAdd(&g_cnt[d.z], 1);
        if ((unsigned)d.w < N_NODES) atomicAdd(&g_cnt[d.w], 1);
    }
}

// single-block scan: 1024 threads, each owns a contiguous segment
__global__ void k_scan() {
    __shared__ int sm[1024];
    const int t   = threadIdx.x;
    const int SEG = (N_NODES + 1023) / 1024;        // 98
    int s    = t * SEG;
    int epos = min(s + SEG, N_NODES);
    int sum = 0;
    for (int i = s; i < epos; i++) sum += g_cnt[i];
    sm[t] = sum;
    for (int d = 1; d < 1024; d <<= 1) {
        __syncthreads();
        int v = (t >= d) ? sm[t - d] : 0;
        __syncthreads();
        sm[t] += v;
    }
    __syncthreads();
    int run = sm[t] - sum;                           // exclusive
    for (int i = s; i < epos; i++) { g_off[i] = run; run += g_cnt[i]; }
    if (t == 1023) g_off[N_NODES] = sm[1023];
}

__global__ void k_dinv_cur() {
    int i = blockIdx.x * blockDim.x + threadIdx.x;
    if (i < N_NODES) {
        g_dinv[i] = rsqrtf((float)(g_cnt[i] + 1));   // deg incl self-loop, >=1
        g_cur[i]  = g_off[i];
    }
}

__global__ void k_fill(const int* __restrict__ ei) {
    int e4 = blockIdx.x * blockDim.x + threadIdx.x;
    if (e4 * 4 < N_EDGES) {
        int4 s = *(const int4*)&ei[e4 * 4];
        int4 d = *(const int4*)&ei[N_EDGES + e4 * 4];
        if ((unsigned)d.x < N_NODES && (unsigned)s.x < N_NODES)
            g_srcs[atomicAdd(&g_cur[d.x], 1)] = s.x;
        if ((unsigned)d.y < N_NODES && (unsigned)s.y < N_NODES)
            g_srcs[atomicAdd(&g_cur[d.y], 1)] = s.y;
        if ((unsigned)d.z < N_NODES && (unsigned)s.z < N_NODES)
            g_srcs[atomicAdd(&g_cur[d.z], 1)] = s.z;
        if ((unsigned)d.w < N_NODES && (unsigned)s.w < N_NODES)
            g_srcs[atomicAdd(&g_cur[d.w], 1)] = s.w;
    }
}

// ---------------- SGEMM body (packed f32x2 FMA), optional dinv epilogue ----------------
template<int BM, int BN, int BK, int TM, int TN, bool SCALE>
__device__ __forceinline__ void gemm_body(
    const float* __restrict__ A, const float* __restrict__ B,
    float* __restrict__ C, int K, int Nc)
{
    constexpr int TX  = BN / TN;
    constexpr int TY  = BM / TM;
    constexpr int NT  = TX * TY;
    constexpr int TN2 = TN / 2;
    __shared__ float As[BK][BM + 4];
    __shared__ __align__(16) float Bs[BK][BN];

    const int tid = threadIdx.x;
    const int tx  = tid % TX;
    const int ty  = tid / TX;
    const int rowBase = blockIdx.x * BM;

    u64 acc2[TM][TN2];
#pragma unroll
    for (int i = 0; i < TM; i++)
#pragma unroll
        for (int j = 0; j < TN2; j++) acc2[i][j] = 0ull;

    for (int kb = 0; kb < K; kb += BK) {
#pragma unroll
        for (int i = tid; i < BM * BK / 4; i += NT) {
            int r  = i / (BK / 4);
            int kq = (i % (BK / 4)) * 4;
            int gr = rowBase + r;
            float4 v = make_float4(0.f, 0.f, 0.f, 0.f);
            if (gr < N_NODES) v = *(const float4*)&A[gr * K + kb + kq];
            As[kq + 0][r] = v.x; As[kq + 1][r] = v.y;
            As[kq + 2][r] = v.z; As[kq + 3][r] = v.w;
        }
#pragma unroll
        for (int i = tid; i < BK * BN / 4; i += NT) {
            int k = (i * 4) / BN;
            int c = (i * 4) % BN;
            *(float4*)&Bs[k][c] = *(const float4*)&B[(kb + k) * Nc + c];
        }
        __syncthreads();
#pragma unroll
        for (int k = 0; k < BK; k++) {
            float a[TM];
#pragma unroll
            for (int i = 0; i < TM; i += 4) *(float4*)&a[i] = *(const float4*)&As[k][ty * TM + i];
            u64 aa[TM];
#pragma unroll
            for (int i = 0; i < TM; i++) aa[i] = pack2(a[i], a[i]);
            u64 bb[TN2];
#pragma unroll
            for (int j = 0; j < TN2; j++) bb[j] = *(const u64*)&Bs[k][tx * TN + 2 * j];
#pragma unroll
            for (int i = 0; i < TM; i++)
#pragma unroll
                for (int j = 0; j < TN2; j++) fma2(acc2[i][j], aa[i], bb[j]);
        }
        __syncthreads();
    }
#pragma unroll
    for (int i = 0; i < TM; i++) {
        int gr = rowBase + ty * TM + i;
        if (gr < N_NODES) {
            float dv = SCALE ? g_dinv[gr] : 1.0f;
#pragma unroll
            for (int j = 0; j < TN2; j += 2) {
                float4 v;
                unpack2(acc2[i][j + 0], v.x, v.y);
                unpack2(acc2[i][j + 1], v.z, v.w);
                if (SCALE) { v.x *= dv; v.y *= dv; v.z *= dv; v.w *= dv; }
                *(float4*)&C[gr * Nc + tx * TN + 2 * j] = v;
            }
        }
    }
}

// layer-1 GEMM: x @ W1 -> g_hs1 (UNSCALED: independent of CSR chain)
__global__ void k_gemm1(const float* __restrict__ x, const float* __restrict__ W1) {
    gemm_body<128, 128, 16, 8, 8, false>(x, W1, g_hs1, F_IN, F_HID);
}

// layer-2 GEMM: g_agg1 @ W2 -> g_hs2 (dinv-scaled in epilogue)
__global__ void k_gemm2(const float* __restrict__ W2) {
    gemm_body<128, 64, 16, 8, 4, true>(g_agg1, W2, g_hs2, F_HID, F_OUT);
}

// ---------------- aggregation: warp per node, gather over CSR ----------------
// layer 1: hs1 is UNSCALED -> apply dinv[src] per edge; width 128, +bias, relu
__global__ void k_agg1(const float* __restrict__ b1) {
    int w    = (blockIdx.x * blockDim.x + threadIdx.x) >> 5;
    int lane = threadIdx.x & 31;
    if (w >= N_NODES) return;
    const float4* hs = (const float4*)g_hs1;      // 32 float4 per row (unscaled)
    float dvw = g_dinv[w];
    float4 h0 = hs[w * 32 + lane];
    float4 acc;                                    // self-loop: dinv[w]*h[w]
    acc.x = h0.x * dvw; acc.y = h0.y * dvw; acc.z = h0.z * dvw; acc.w = h0.w * dvw;
    int e  = g_off[w];
    int e1 = g_off[w + 1];
    for (; e + 7 < e1; e += 8) {
        int s[8];
#pragma unroll
        for (int q = 0; q < 8; q++) s[q] = g_srcs[e + q];
        float dv[8];
#pragma unroll
        for (int q = 0; q < 8; q++) dv[q] = g_dinv[s[q]];     // lane-uniform broadcast
        float4 v[8];
#pragma unroll
        for (int q = 0; q < 8; q++) v[q] = hs[s[q] * 32 + lane];
#pragma unroll
        for (int q = 0; q < 8; q++) {
            acc.x = fmaf(v[q].x, dv[q], acc.x);
            acc.y = fmaf(v[q].y, dv[q], acc.y);
            acc.z = fmaf(v[q].z, dv[q], acc.z);
            acc.w = fmaf(v[q].w, dv[q], acc.w);
        }
    }
    for (; e < e1; e++) {
        int s = g_srcs[e];
        float dv = g_dinv[s];
        float4 v = hs[s * 32 + lane];
        acc.x = fmaf(v.x, dv, acc.x);
        acc.y = fmaf(v.y, dv, acc.y);
        acc.z = fmaf(v.z, dv, acc.z);
        acc.w = fmaf(v.w, dv, acc.w);
    }
    float4 bb = ((const float4*)b1)[lane];
    float4 o;
    o.x = fmaxf(fmaf(acc.x, dvw, bb.x), 0.f);
    o.y = fmaxf(fmaf(acc.y, dvw, bb.y), 0.f);
    o.z = fmaxf(fmaf(acc.z, dvw, bb.z), 0.f);
    o.w = fmaxf(fmaf(acc.w, dvw, bb.w), 0.f);
    ((float4*)g_agg1)[w * 32 + lane] = o;
}

// layer 2: hs2 pre-scaled; width 64, +bias, writes d_out
__global__ void k_agg2(const float* __restrict__ b2, float* __restrict__ out) {
    int w    = (blockIdx.x * blockDim.x + threadIdx.x) >> 5;
    int lane = threadIdx.x & 31;
    if (w >= N_NODES) return;
    const float2* hs = (const float2*)g_hs2;      // 32 float2 per row
    float2 acc = hs[w * 32 + lane];               // self-loop term (pre-scaled)
    int e  = g_off[w];
    int e1 = g_off[w + 1];
    for (; e + 7 < e1; e += 8) {
        int s[8];
#pragma unroll
        for (int q = 0; q < 8; q++) s[q] = g_srcs[e + q];
        float2 v[8];
#pragma unroll
        for (int q = 0; q < 8; q++) v[q] = hs[s[q] * 32 + lane];
#pragma unroll
        for (int q = 0; q < 8; q++) { acc.x += v[q].x; acc.y += v[q].y; }
    }
    for (; e < e1; e++) {
        int s = g_srcs[e];
        float2 v = hs[s * 32 + lane];
        acc.x += v.x; acc.y += v.y;
    }
    float dv = g_dinv[w];
    float2 bb = ((const float2*)b2)[lane];
    float2 o;
    o.x = fmaf(acc.x, dv, bb.x);
    o.y = fmaf(acc.y, dv, bb.y);
    ((float2*)out)[w * 32 + lane] = o;
}

// ---------------- launcher ----------------
extern "C" void kernel_launch(void* const* d_in, const int* in_sizes, int n_in,
                              void* d_out, int out_size) {
    const float* x  = (const float*)d_in[0];
    const int*   ei = (const int*)d_in[1];
    const float* W1 = (const float*)d_in[2];
    const float* b1 = (const float*)d_in[3];
    const float* W2 = (const float*)d_in[4];
    const float* b2 = (const float*)d_in[5];
    float* out = (float*)d_out;

    const int NB_N  = (N_NODES + 255) / 256;
    const int NB_E4 = (N_EDGES / 4 + 255) / 256;

    // fork: CSR build on s2, GEMM1 on the main (captured) stream
    cudaEventRecord(g_hx.evFork, 0);
    cudaStreamWaitEvent(g_hx.s2, g_hx.evFork, 0);

    k_zero_cnt<<<NB_N, 256, 0, g_hx.s2>>>();
    k_hist    <<<NB_E4, 256, 0, g_hx.s2>>>(ei);
    k_scan    <<<1, 1024, 0, g_hx.s2>>>();
    k_dinv_cur<<<NB_N, 256, 0, g_hx.s2>>>();
    k_fill    <<<NB_E4, 256, 0, g_hx.s2>>>(ei);
    cudaEventRecord(g_hx.evJoin, g_hx.s2);

    k_gemm1<<<(N_NODES + 127) / 128, 256>>>(x, W1);

    // join
    cudaStreamWaitEvent(0, g_hx.evJoin, 0);

    k_agg1<<<(N_NODES + 7) / 8, 256>>>(b1);
    k_gemm2<<<(N_NODES + 127) / 128, 256>>>(W2);
    k_agg2<<<(N_NODES + 7) / 8, 256>>>(b2, out);
}